// round 6
// baseline (speedup 1.0000x reference)
#include <cuda_runtime.h>

// out[b,:] = (cnt>0) ? sum_c w[b,c] * F[i0(b,c),:] * F[i1(b,c),:]  :  F[b,:]
// D = 128. One warp per target; lane owns a float4 (4 dims).
//
// Geometry: 148 blocks x 1024 thr, each block owns a CONTIGUOUS target chunk
// so its gather window (~chunk+400 rows) stays L1-resident (R4: L2 at 8.8%).
//
// MIO diet: gathers are 4 LDG.128 (16 wavefronts) per 2 combos — irreducible.
// Index pairs come via warp-uniform __ldg (1 broadcast wavefront, 16 combos
// per 128B line) instead of 2 shuffles; only the weight is shuffled from the
// ballot pass's registers. Trip count by ballot (padding trailing, w > 0 real).

#define THREADS 1024
#define FULL 0xffffffffu

__global__ __launch_bounds__(THREADS)
void tmp_kernel(const float* __restrict__ features,
                const int2*  __restrict__ comb_idx,   // [B, C] int2 pairs
                const float* __restrict__ comb_w,     // [B, C]
                float*       __restrict__ out,        // [B, 128]
                int B, int C, int chunk)
{
    const int warp = threadIdx.x >> 5;   // 0..31
    const int lane = threadIdx.x & 31;
    const int start = blockIdx.x * chunk;
    const int end   = min(start + chunk, B);

    const float4* __restrict__ f4 = reinterpret_cast<const float4*>(features);

    for (int b = start + warp; b < end; b += 32) {
        float4 acc = make_float4(0.f, 0.f, 0.f, 0.f);

        const long base = (long)b * C;
        const int2*  __restrict__ ci = comb_idx + base;
        const float* __restrict__ cw = comb_w + base;

        int total = 0;
        for (int c0 = 0; c0 < C; c0 += 32) {
            const int m = c0 + lane;
            float w = 0.0f;
            if (m < C) w = __ldg(cw + m);
            const unsigned nz = __ballot_sync(FULL, w != 0.0f);
            const int cnt = (nz == FULL) ? 32 : (__ffs(~nz) - 1);
            const int cnt2 = (cnt + 1) & ~1;   // pad combo has w=0 -> contributes 0

            for (int j = 0; j < cnt2; j += 2) {
                const float w0 = __shfl_sync(FULL, w, j);
                const float w1 = __shfl_sync(FULL, w, j + 1);
                // warp-uniform index loads (broadcast, line-hot)
                const int2 p0 = __ldg(ci + (c0 + j));
                const int2 p1 = __ldg(ci + min(c0 + j + 1, C - 1)); // clamp: pad-safe

                const float4 a0 = __ldg(f4 + (long)p0.x * 32 + lane);
                const float4 v0 = __ldg(f4 + (long)p0.y * 32 + lane);
                const float4 a1 = __ldg(f4 + (long)p1.x * 32 + lane);
                const float4 v1 = __ldg(f4 + (long)p1.y * 32 + lane);

                acc.x = fmaf(w0, a0.x * v0.x, acc.x);
                acc.y = fmaf(w0, a0.y * v0.y, acc.y);
                acc.z = fmaf(w0, a0.z * v0.z, acc.z);
                acc.w = fmaf(w0, a0.w * v0.w, acc.w);
                acc.x = fmaf(w1, a1.x * v1.x, acc.x);
                acc.y = fmaf(w1, a1.y * v1.y, acc.y);
                acc.z = fmaf(w1, a1.z * v1.z, acc.z);
                acc.w = fmaf(w1, a1.w * v1.w, acc.w);
            }

            total += cnt;
            if (cnt < 32) break;   // trailing padding reached
        }

        if (total == 0) {
            acc = __ldg(f4 + (long)b * 32 + lane);   // self-feature fallback
        }

        reinterpret_cast<float4*>(out)[(long)b * 32 + lane] = acc;
    }
}

extern "C" void kernel_launch(void* const* d_in, const int* in_sizes, int n_in,
                              void* d_out, int out_size)
{
    const float* features = (const float*)d_in[0];
    // d_in[1] = target_nodes (== arange(B)); unused.
    const int2*  comb_idx = (const int2*)d_in[2];
    const float* comb_w   = (const float*)d_in[3];
    float* out = (float*)d_out;

    const int B = in_sizes[4];            // has_edge element count
    const int C = in_sizes[3] / B;        // comb_w is [B, C]

    const int NSM = 148;
    const int chunk = (B + NSM - 1) / NSM;          // contiguous targets per block
    const int blocks = (B + chunk - 1) / chunk;

    tmp_kernel<<<blocks, THREADS>>>(features, comb_idx, comb_w, out, B, C, chunk);
}